// round 16
// baseline (speedup 1.0000x reference)
#include <cuda_runtime.h>
#include <cuda_fp16.h>
#include <cstdint>

// ---------------- problem constants ----------------
// xs: [16,128,24,24,24] f32 ; fv: [128,128,3,3,3] f32 ; out: [16,128,22,22,22] f32
#define BATCH 16
#define CHAN  128
#define NF    128
#define SP_IN   13824          // 24^3
#define SP_OUT  10648          // 22^3
#define NPOS    170368         // 16*10648
#define NCHUNK  54             // 27 offsets * 2 half-C chunks (K=64 each)

// tile split: 1184 full 128x128 tiles + 294 half 128x64 tiles (fill the tail wave)
#define NFULL   1184
#define FULLPOS 151552         // 1184*128
#define NHALF   294            // (NPOS-FULLPOS)/64
#define NGRID   (NFULL + NHALF)

#define XBLKS   9216           // 16*576 xprep blocks; weight blocks appended after

// ---------------- device scratch ----------------
__device__ __half g_Xh[BATCH * SP_IN * CHAN];   // channels-last f16
__device__ float  g_S [BATCH * SP_IN];          // per-voxel sum_c x^2
__device__ __half g_Wh[27 * NF * CHAN];         // [off][f][c]
__device__ float  g_p2[NF];

// smem: [0,512) x2s[128] ; [512,1024) p2s[128] ; [1024,1536) nbs ; [1536,2048) nss ;
//       [2048, +3*32768) stages (A 16KB + B 16KB each)
#define OFF_STAGE 2048
#define SMEM_BYTES (OFF_STAGE + 3 * 32768)

// ---------------- PTX helpers ----------------
__device__ __forceinline__ uint32_t smem_u32(const void* p) {
    uint32_t a;
    asm("{ .reg .u64 t; cvta.to.shared.u64 t, %1; cvt.u32.u64 %0, t; }" : "=r"(a) : "l"(p));
    return a;
}
__device__ __forceinline__ void cp16(uint32_t dst, const void* src) {
    asm volatile("cp.async.cg.shared.global [%0], [%1], 16;" :: "r"(dst), "l"(src) : "memory");
}
#define CP_COMMIT() asm volatile("cp.async.commit_group;" ::: "memory")
#define CP_WAIT1()  asm volatile("cp.async.wait_group 1;"  ::: "memory")

__device__ __forceinline__ void ldsm4(uint32_t (&r)[4], uint32_t addr) {
    asm volatile("ldmatrix.sync.aligned.m8n8.x4.shared.b16 {%0,%1,%2,%3}, [%4];"
                 : "=r"(r[0]), "=r"(r[1]), "=r"(r[2]), "=r"(r[3]) : "r"(addr));
}
__device__ __forceinline__ void mma_h(uint32_t* c, const uint32_t* a, const uint32_t* b) {
    asm volatile("mma.sync.aligned.m16n8k16.row.col.f16.f16.f16.f16 "
                 "{%0,%1}, {%2,%3,%4,%5}, {%6,%7}, {%0,%1};"
                 : "+r"(c[0]), "+r"(c[1])
                 : "r"(a[0]), "r"(a[1]), "r"(a[2]), "r"(a[3]), "r"(b[0]), "r"(b[1]));
}
__device__ __forceinline__ float fast_sqrt(float x) {
    float r;
    asm("sqrt.approx.f32 %0, %1;" : "=f"(r) : "f"(x));
    return r;
}

// ---------------- fused pre-pass ----------------
// blocks [0, XBLKS):        X -> channels-last f16 + sum of squares (R15 xprep, unchanged)
// blocks [XBLKS, XBLKS+NF): weights -> [off][f][c] f16 AND ||p||^2 (R15 wp2, unchanged)
__global__ void __launch_bounds__(256) prep_kernel(const float* __restrict__ xs,
                                                   const float* __restrict__ fv) {
    __shared__ float tile[CHAN * 29];
    const int t = threadIdx.x;

    if (blockIdx.x >= XBLKS) {
        // ---- weight path (one block per feature f, first 128 threads active) ----
        __shared__ float red[4];
        const int f = blockIdx.x - XBLKS;
        if (t < 128) {
            const float* src = fv + (long)f * 3456;
            float s = 0.f;
            #pragma unroll
            for (int k = 0; k < 27; k++) {
                const int idx = k * 128 + t;          // = c*27 + off
                const float v = src[idx];             // coalesced
                s += v * v;
                const int c   = idx / 27;
                const int off = idx - c * 27;
                g_Wh[off * (NF * CHAN) + f * CHAN + c] = __float2half(v);
            }
            #pragma unroll
            for (int o = 16; o > 0; o >>= 1) s += __shfl_down_sync(0xffffffffu, s, o);
            if ((t & 31) == 0) red[t >> 5] = s;
        }
        __syncthreads();
        if (t == 0) g_p2[f] = red[0] + red[1] + red[2] + red[3];
        return;
    }

    // ---- X path (identical to R15 xprep) ----
    const int blk = blockIdx.x;                 // b*576 + (d*24+h)
    const int b   = blk / 576;
    const long inbase = (long)b * CHAN * SP_IN + (long)(blk - b * 576) * 24;

    const int c  = t >> 1;
    const int h2 = (t & 1) * 12;
    const float4* src = (const float4*)(xs + inbase + (long)c * SP_IN + h2);
    float4 v0 = src[0], v1 = src[1], v2 = src[2];
    float* dst = tile + c * 29 + h2;
    dst[0]=v0.x; dst[1]=v0.y; dst[2]=v0.z;  dst[3]=v0.w;
    dst[4]=v1.x; dst[5]=v1.y; dst[6]=v1.z;  dst[7]=v1.w;
    dst[8]=v2.x; dst[9]=v2.y; dst[10]=v2.z; dst[11]=v2.w;
    __syncthreads();

    const int spb = blk * 24;
    #pragma unroll
    for (int k = 0; k < 6; k++) {
        const int i  = t + k * 256;           // 0..1535
        const int cc = (i & 63) * 2;
        const int w  = i >> 6;
        __half2 p = __floats2half2_rn(tile[cc * 29 + w], tile[(cc + 1) * 29 + w]);
        *(__half2*)(g_Xh + (long)(spb + w) * CHAN + cc) = p;
    }
    if (t < 24) {
        float s = 0.f;
        #pragma unroll 8
        for (int cc = 0; cc < CHAN; cc++) { float v = tile[cc * 29 + t]; s += v * v; }
        g_S[spb + t] = s;
    }
}

// ---------------- tile body (templated on N tile size BN = 128 or 64) ----------------
// 128 thr = 4 warps (2x2), warp tile 64 x (BN/2), CTA tile 128 x BN, 3-stage pipeline.
template<int BN>
__device__ __forceinline__ void l2_tile(float* __restrict__ out, char* smem, int tile_base) {
    constexpr int NR  = BN / 16;    // B rows per thread (8 or 4)
    constexpr int NBF = BN / 32;    // B frags per kk  (4 or 2)
    const uint32_t sb = smem_u32(smem);
    const int tid  = threadIdx.x;
    const int wid  = tid >> 5;
    const int lane = tid & 31;

    float* x2s = (float*)(smem);
    float* p2s = (float*)(smem + 512);
    int*   nbs = (int*)(smem + 1024);
    int*   nss = (int*)(smem + 1536);
    const uint32_t stg = sb + OFF_STAGE;
    const int seg = tid & 7;

    // im2col row bases first (needed by issue)
    int rbase[NR];
    #pragma unroll
    for (int i = 0; i < NR; i++) {
        int n = tile_base + (tid >> 3) + 16 * i;
        int b = n / SP_OUT;  int rem = n - b * SP_OUT;
        int z = rem / 484;   int r2  = rem - z * 484;
        int y = r2 / 22;     int x   = r2 - y * 22;
        rbase[i] = (((b * 24 + z) * 24 + y) * 24 + x) * CHAN;
    }

    auto issue = [&](int chunk) {
        const int st    = chunk % 3;
        const int off   = chunk >> 1;
        const int chalf = chunk & 1;
        const int kd = off / 9, kr = off - kd * 9;
        const int kh = kr / 3,  kw = kr - kh * 3;
        const int offterm = (kd * 576 + kh * 24 + kw) * CHAN + chalf * 64 + seg * 8;
        const __half* wsrc = g_Wh + off * (NF * CHAN) + chalf * 64 + seg * 8;
        const uint32_t sA = stg + st * 32768;
        const uint32_t sB = sA + 16384;
        #pragma unroll
        for (int i = 0; i < 8; i++) {          // A: always 128 rows
            const int r = (tid >> 3) + 16 * i;
            uint32_t so = (uint32_t)(r * 128 + seg * 16);
            so ^= (so >> 3) & 0x70;
            cp16(sA + so, wsrc + r * CHAN);
        }
        #pragma unroll
        for (int i = 0; i < NR; i++) {         // B: BN rows
            const int r = (tid >> 3) + 16 * i;
            uint32_t so = (uint32_t)(r * 128 + seg * 16);
            so ^= (so >> 3) & 0x70;
            cp16(sB + so, g_Xh + rbase[i] + offterm);
        }
    };

    // fire the pipeline immediately; metadata below overlaps the cp.async latency
    issue(0); CP_COMMIT();
    issue(1); CP_COMMIT();

    // per-position metadata (ordered before use by the chunk-0 __syncthreads)
    p2s[tid] = g_p2[tid];
    if (tid < BN) {
        int n = tile_base + tid;
        int b = n / SP_OUT;  int rem = n - b * SP_OUT;
        int z = rem / 484;   int r2  = rem - z * 484;
        int y = r2 / 22;     int x   = r2 - y * 22;
        nbs[tid] = b;  nss[tid] = rem;
        int spb = ((b * 24 + z) * 24 + y) * 24 + x;
        float s = 0.f;
        #pragma unroll
        for (int kd = 0; kd < 3; kd++)
            #pragma unroll
            for (int kh = 0; kh < 3; kh++)
                #pragma unroll
                for (int kw = 0; kw < 3; kw++)
                    s += g_S[spb + kd * 576 + kh * 24 + kw];
        x2s[tid] = s;
    }

    const int wm = wid >> 1, wn = wid & 1;     // 2 x 2 warp grid
    const int arow = wm * 64 + (lane & 15);
    const int asg  = lane >> 4;
    const int brow = wn * (BN / 2) + ((lane >> 4) & 1) * 8 + (lane & 7);
    const int bsg  = (lane >> 3) & 1;

    uint32_t acc[4][2 * NBF][2];
    #pragma unroll
    for (int mt = 0; mt < 4; mt++)
        #pragma unroll
        for (int nt = 0; nt < 2 * NBF; nt++) { acc[mt][nt][0] = 0u; acc[mt][nt][1] = 0u; }

    uint32_t a[2][4][4], b[2][NBF][4];
    auto loadfrag = [&](int buf, int kk, uint32_t aB, uint32_t bB) {
        #pragma unroll
        for (int mt = 0; mt < 4; mt++) {
            const int R = arow + mt * 16;
            ldsm4(a[buf][mt], aB + (uint32_t)(R * 128 + (((kk * 2 + asg) ^ (R & 7)) * 16)));
        }
        #pragma unroll
        for (int np = 0; np < NBF; np++) {
            const int R = brow + np * 16;
            ldsm4(b[buf][np], bB + (uint32_t)(R * 128 + (((kk * 2 + bsg) ^ (R & 7)) * 16)));
        }
    };

    for (int chunk = 0; chunk < NCHUNK; chunk++) {
        CP_WAIT1();
        __syncthreads();
        // stage (chunk+2)%3 == (chunk-1)%3: its readers all passed the sync above -> safe
        if (chunk + 2 < NCHUNK) issue(chunk + 2);
        CP_COMMIT();
        const uint32_t aB = stg + (chunk % 3) * 32768;
        const uint32_t bB = aB + 16384;
        loadfrag(0, 0, aB, bB);
        #pragma unroll
        for (int kk = 0; kk < 4; kk++) {
            const int cur = kk & 1;
            if (kk < 3) loadfrag(cur ^ 1, kk + 1, aB, bB);   // prefetch next-k frags
            #pragma unroll
            for (int mt = 0; mt < 4; mt++)
                #pragma unroll
                for (int np = 0; np < NBF; np++) {
                    mma_h(acc[mt][2 * np],     a[cur][mt], &b[cur][np][0]);
                    mma_h(acc[mt][2 * np + 1], a[cur][mt], &b[cur][np][2]);
                }
        }
    }

    // ---- epilogue: direct store from accumulators (STG.64 over n-pairs) ----
    float p2r[8];
    #pragma unroll
    for (int mt = 0; mt < 4; mt++) {
        const int m0 = wm * 64 + mt * 16 + (lane >> 2);
        p2r[2 * mt]     = p2s[m0];
        p2r[2 * mt + 1] = p2s[m0 + 8];
    }
    #pragma unroll
    for (int nt = 0; nt < 2 * NBF; nt++) {
        const int n0 = wn * (BN / 2) + nt * 8 + (lane & 3) * 2;
        const float2 x2v = *(const float2*)&x2s[n0];
        const long base = (long)nbs[n0] * (NF * SP_OUT) + nss[n0];
        #pragma unroll
        for (int mt = 0; mt < 4; mt++) {
            const int m0 = wm * 64 + mt * 16 + (lane >> 2);
            const float2 c0 = __half22float2(*(__half2*)&acc[mt][nt][0]);
            const float2 c1 = __half22float2(*(__half2*)&acc[mt][nt][1]);
            float2 o0, o1;
            o0.x = fast_sqrt(fabsf(x2v.x + p2r[2 * mt]     - 2.0f * c0.x) + 1e-14f);
            o0.y = fast_sqrt(fabsf(x2v.y + p2r[2 * mt]     - 2.0f * c0.y) + 1e-14f);
            o1.x = fast_sqrt(fabsf(x2v.x + p2r[2 * mt + 1] - 2.0f * c1.x) + 1e-14f);
            o1.y = fast_sqrt(fabsf(x2v.y + p2r[2 * mt + 1] - 2.0f * c1.y) + 1e-14f);
            *(float2*)&out[base + (long)m0 * SP_OUT]       = o0;
            *(float2*)&out[base + (long)(m0 + 8) * SP_OUT] = o1;
        }
    }
}

__global__ void __launch_bounds__(128, 2) l2conv_main_kernel(float* __restrict__ out) {
    extern __shared__ char smem[];
    if (blockIdx.x < NFULL)
        l2_tile<128>(out, smem, blockIdx.x * 128);
    else
        l2_tile<64>(out, smem, FULLPOS + (blockIdx.x - NFULL) * 64);
}

// ---------------- launch ----------------
extern "C" void kernel_launch(void* const* d_in, const int* in_sizes, int n_in,
                              void* d_out, int out_size) {
    const float* xs = (const float*)d_in[0];
    const float* fv = (const float*)d_in[1];
    if (n_in >= 2 && in_sizes[0] == 128 * 128 * 27) {  // robust to input ordering
        xs = (const float*)d_in[1];
        fv = (const float*)d_in[0];
    }
    cudaFuncSetAttribute(l2conv_main_kernel,
                         cudaFuncAttributeMaxDynamicSharedMemorySize, SMEM_BYTES);
    // max smem carveout so 8 prep blocks (120KB static smem total) fit per SM
    cudaFuncSetAttribute(prep_kernel,
                         cudaFuncAttributePreferredSharedMemoryCarveout, 100);
    prep_kernel<<<XBLKS + NF, 256>>>(xs, fv);
    l2conv_main_kernel<<<NGRID, 128, SMEM_BYTES>>>((float*)d_out);
}

// round 17
// speedup vs baseline: 1.0564x; 1.0564x over previous
#include <cuda_runtime.h>
#include <cuda_fp16.h>
#include <cstdint>

// ---------------- problem constants ----------------
// xs: [16,128,24,24,24] f32 ; fv: [128,128,3,3,3] f32 ; out: [16,128,22,22,22] f32
#define BATCH 16
#define CHAN  128
#define NF    128
#define SP_IN   13824          // 24^3
#define SP_OUT  10648          // 22^3
#define NPOS    170368         // 16*10648
#define NCHUNK  54             // 27 offsets * 2 half-C chunks (K=64 each)

// tile split: 1184 full 128x128 tiles + 294 half 128x64 tiles (fill the tail wave)
#define NFULL   1184
#define FULLPOS 151552         // 1184*128
#define NHALF   294            // (NPOS-FULLPOS)/64
#define NGRID   (NFULL + NHALF)

// ---------------- device scratch ----------------
__device__ __half g_Xh[BATCH * SP_IN * CHAN];   // channels-last f16
__device__ float  g_S [BATCH * SP_IN];          // per-voxel sum_c x^2
__device__ __half g_Wh[27 * NF * CHAN];         // [off][f][c]
__device__ float  g_p2[NF];

// smem: [0,512) x2s[128] ; [512,1024) p2s[128] ; [1024,1536) nbs ; [1536,2048) nss ;
//       [2048, +3*32768) stages (A 16KB + B 16KB each)
#define OFF_STAGE 2048
#define SMEM_BYTES (OFF_STAGE + 3 * 32768)

// ---------------- PTX helpers ----------------
__device__ __forceinline__ uint32_t smem_u32(const void* p) {
    uint32_t a;
    asm("{ .reg .u64 t; cvta.to.shared.u64 t, %1; cvt.u32.u64 %0, t; }" : "=r"(a) : "l"(p));
    return a;
}
__device__ __forceinline__ void cp16(uint32_t dst, const void* src) {
    asm volatile("cp.async.cg.shared.global [%0], [%1], 16;" :: "r"(dst), "l"(src) : "memory");
}
#define CP_COMMIT() asm volatile("cp.async.commit_group;" ::: "memory")
#define CP_WAIT1()  asm volatile("cp.async.wait_group 1;"  ::: "memory")

__device__ __forceinline__ void ldsm4(uint32_t (&r)[4], uint32_t addr) {
    asm volatile("ldmatrix.sync.aligned.m8n8.x4.shared.b16 {%0,%1,%2,%3}, [%4];"
                 : "=r"(r[0]), "=r"(r[1]), "=r"(r[2]), "=r"(r[3]) : "r"(addr));
}
__device__ __forceinline__ void mma_h(uint32_t* c, const uint32_t* a, const uint32_t* b) {
    asm volatile("mma.sync.aligned.m16n8k16.row.col.f16.f16.f16.f16 "
                 "{%0,%1}, {%2,%3,%4,%5}, {%6,%7}, {%0,%1};"
                 : "+r"(c[0]), "+r"(c[1])
                 : "r"(a[0]), "r"(a[1]), "r"(a[2]), "r"(a[3]), "r"(b[0]), "r"(b[1]));
}
__device__ __forceinline__ float fast_sqrt(float x) {
    float r;
    asm("sqrt.approx.f32 %0, %1;" : "=f"(r) : "f"(x));
    return r;
}

// ---------------- pre-pass 1: X -> channels-last f16 + sum of squares ----------------
// f16 smem tile (stride 26): 6.7KB/block -> 8 resident blocks (thread-limit), ~100% occ.
__global__ void __launch_bounds__(256) xprep_kernel(const float* __restrict__ xs) {
    __shared__ __half tile[CHAN * 26];
    const int blk = blockIdx.x;                 // b*576 + (d*24+h)
    const int t   = threadIdx.x;
    const int b   = blk / 576;
    const long inbase = (long)b * CHAN * SP_IN + (long)(blk - b * 576) * 24;

    const int c  = t >> 1;
    const int h2 = (t & 1) * 12;
    const float4* src = (const float4*)(xs + inbase + (long)c * SP_IN + h2);
    float4 v0 = src[0], v1 = src[1], v2 = src[2];
    __half* dst = tile + c * 26 + h2;           // (c*26+h2)*2 bytes, 4B-aligned (h2 even)
    *(__half2*)(dst + 0)  = __floats2half2_rn(v0.x, v0.y);
    *(__half2*)(dst + 2)  = __floats2half2_rn(v0.z, v0.w);
    *(__half2*)(dst + 4)  = __floats2half2_rn(v1.x, v1.y);
    *(__half2*)(dst + 6)  = __floats2half2_rn(v1.z, v1.w);
    *(__half2*)(dst + 8)  = __floats2half2_rn(v2.x, v2.y);
    *(__half2*)(dst + 10) = __floats2half2_rn(v2.z, v2.w);
    __syncthreads();

    const int spb = blk * 24;
    #pragma unroll
    for (int k = 0; k < 6; k++) {
        const int i  = t + k * 256;           // 0..1535
        const int cc = (i & 63) * 2;
        const int w  = i >> 6;
        __half2 p = __halves2half2(tile[cc * 26 + w], tile[(cc + 1) * 26 + w]);
        *(__half2*)(g_Xh + (long)(spb + w) * CHAN + cc) = p;
    }
    if (t < 24) {
        float s = 0.f;
        #pragma unroll 8
        for (int cc = 0; cc < CHAN; cc++) {
            float v = __half2float(tile[cc * 26 + t]);
            s += v * v;                        // matches the f16 values the GEMM uses
        }
        g_S[spb + t] = s;
    }
}

// ---------------- pre-pass 2 (fused): weights -> [off][f][c] f16 AND ||p||^2 ----------------
__global__ void __launch_bounds__(128) wp2_kernel(const float* __restrict__ fv) {
    __shared__ float red[4];
    const int f = blockIdx.x;
    const int t = threadIdx.x;
    const float* src = fv + (long)f * 3456;
    float s = 0.f;
    #pragma unroll
    for (int k = 0; k < 27; k++) {
        const int idx = k * 128 + t;          // = c*27 + off
        const float v = src[idx];             // coalesced
        s += v * v;
        const int c   = idx / 27;
        const int off = idx - c * 27;
        g_Wh[off * (NF * CHAN) + f * CHAN + c] = __float2half(v);
    }
    #pragma unroll
    for (int o = 16; o > 0; o >>= 1) s += __shfl_down_sync(0xffffffffu, s, o);
    if ((t & 31) == 0) red[t >> 5] = s;
    __syncthreads();
    if (t == 0) g_p2[f] = red[0] + red[1] + red[2] + red[3];
}

// ---------------- tile body (templated on N tile size BN = 128 or 64) ----------------
// 128 thr = 4 warps (2x2), warp tile 64 x (BN/2), CTA tile 128 x BN, 3-stage pipeline.
template<int BN>
__device__ __forceinline__ void l2_tile(float* __restrict__ out, char* smem, int tile_base) {
    constexpr int NR  = BN / 16;    // B rows per thread (8 or 4)
    constexpr int NBF = BN / 32;    // B frags per kk  (4 or 2)
    const uint32_t sb = smem_u32(smem);
    const int tid  = threadIdx.x;
    const int wid  = tid >> 5;
    const int lane = tid & 31;

    float* x2s = (float*)(smem);
    float* p2s = (float*)(smem + 512);
    int*   nbs = (int*)(smem + 1024);
    int*   nss = (int*)(smem + 1536);
    const uint32_t stg = sb + OFF_STAGE;
    const int seg = tid & 7;

    // im2col row bases first (needed by issue)
    int rbase[NR];
    #pragma unroll
    for (int i = 0; i < NR; i++) {
        int n = tile_base + (tid >> 3) + 16 * i;
        int b = n / SP_OUT;  int rem = n - b * SP_OUT;
        int z = rem / 484;   int r2  = rem - z * 484;
        int y = r2 / 22;     int x   = r2 - y * 22;
        rbase[i] = (((b * 24 + z) * 24 + y) * 24 + x) * CHAN;
    }

    auto issue = [&](int chunk) {
        const int st    = chunk % 3;
        const int off   = chunk >> 1;
        const int chalf = chunk & 1;
        const int kd = off / 9, kr = off - kd * 9;
        const int kh = kr / 3,  kw = kr - kh * 3;
        const int offterm = (kd * 576 + kh * 24 + kw) * CHAN + chalf * 64 + seg * 8;
        const __half* wsrc = g_Wh + off * (NF * CHAN) + chalf * 64 + seg * 8;
        const uint32_t sA = stg + st * 32768;
        const uint32_t sB = sA + 16384;
        #pragma unroll
        for (int i = 0; i < 8; i++) {          // A: always 128 rows
            const int r = (tid >> 3) + 16 * i;
            uint32_t so = (uint32_t)(r * 128 + seg * 16);
            so ^= (so >> 3) & 0x70;
            cp16(sA + so, wsrc + r * CHAN);
        }
        #pragma unroll
        for (int i = 0; i < NR; i++) {         // B: BN rows
            const int r = (tid >> 3) + 16 * i;
            uint32_t so = (uint32_t)(r * 128 + seg * 16);
            so ^= (so >> 3) & 0x70;
            cp16(sB + so, g_Xh + rbase[i] + offterm);
        }
    };

    // fire the pipeline immediately; metadata below overlaps the cp.async latency
    issue(0); CP_COMMIT();
    issue(1); CP_COMMIT();

    // per-position metadata (ordered before use by the chunk-0 __syncthreads)
    p2s[tid] = g_p2[tid];
    if (tid < BN) {
        int n = tile_base + tid;
        int b = n / SP_OUT;  int rem = n - b * SP_OUT;
        int z = rem / 484;   int r2  = rem - z * 484;
        int y = r2 / 22;     int x   = r2 - y * 22;
        nbs[tid] = b;  nss[tid] = rem;
        int spb = ((b * 24 + z) * 24 + y) * 24 + x;
        float s = 0.f;
        #pragma unroll
        for (int kd = 0; kd < 3; kd++)
            #pragma unroll
            for (int kh = 0; kh < 3; kh++)
                #pragma unroll
                for (int kw = 0; kw < 3; kw++)
                    s += g_S[spb + kd * 576 + kh * 24 + kw];
        x2s[tid] = s;
    }

    const int wm = wid >> 1, wn = wid & 1;     // 2 x 2 warp grid
    const int arow = wm * 64 + (lane & 15);
    const int asg  = lane >> 4;
    const int brow = wn * (BN / 2) + ((lane >> 4) & 1) * 8 + (lane & 7);
    const int bsg  = (lane >> 3) & 1;

    uint32_t acc[4][2 * NBF][2];
    #pragma unroll
    for (int mt = 0; mt < 4; mt++)
        #pragma unroll
        for (int nt = 0; nt < 2 * NBF; nt++) { acc[mt][nt][0] = 0u; acc[mt][nt][1] = 0u; }

    uint32_t a[2][4][4], b[2][NBF][4];
    auto loadfrag = [&](int buf, int kk, uint32_t aB, uint32_t bB) {
        #pragma unroll
        for (int mt = 0; mt < 4; mt++) {
            const int R = arow + mt * 16;
            ldsm4(a[buf][mt], aB + (uint32_t)(R * 128 + (((kk * 2 + asg) ^ (R & 7)) * 16)));
        }
        #pragma unroll
        for (int np = 0; np < NBF; np++) {
            const int R = brow + np * 16;
            ldsm4(b[buf][np], bB + (uint32_t)(R * 128 + (((kk * 2 + bsg) ^ (R & 7)) * 16)));
        }
    };

    for (int chunk = 0; chunk < NCHUNK; chunk++) {
        CP_WAIT1();
        __syncthreads();
        // stage (chunk+2)%3 == (chunk-1)%3: its readers all passed the sync above -> safe
        if (chunk + 2 < NCHUNK) issue(chunk + 2);
        CP_COMMIT();
        const uint32_t aB = stg + (chunk % 3) * 32768;
        const uint32_t bB = aB + 16384;
        loadfrag(0, 0, aB, bB);
        #pragma unroll
        for (int kk = 0; kk < 4; kk++) {
            const int cur = kk & 1;
            if (kk < 3) loadfrag(cur ^ 1, kk + 1, aB, bB);   // prefetch next-k frags
            #pragma unroll
            for (int mt = 0; mt < 4; mt++)
                #pragma unroll
                for (int np = 0; np < NBF; np++) {
                    mma_h(acc[mt][2 * np],     a[cur][mt], &b[cur][np][0]);
                    mma_h(acc[mt][2 * np + 1], a[cur][mt], &b[cur][np][2]);
                }
        }
    }

    // ---- epilogue: direct store from accumulators (STG.64 over n-pairs) ----
    float p2r[8];
    #pragma unroll
    for (int mt = 0; mt < 4; mt++) {
        const int m0 = wm * 64 + mt * 16 + (lane >> 2);
        p2r[2 * mt]     = p2s[m0];
        p2r[2 * mt + 1] = p2s[m0 + 8];
    }
    #pragma unroll
    for (int nt = 0; nt < 2 * NBF; nt++) {
        const int n0 = wn * (BN / 2) + nt * 8 + (lane & 3) * 2;
        const float2 x2v = *(const float2*)&x2s[n0];
        const long base = (long)nbs[n0] * (NF * SP_OUT) + nss[n0];
        #pragma unroll
        for (int mt = 0; mt < 4; mt++) {
            const int m0 = wm * 64 + mt * 16 + (lane >> 2);
            const float2 c0 = __half22float2(*(__half2*)&acc[mt][nt][0]);
            const float2 c1 = __half22float2(*(__half2*)&acc[mt][nt][1]);
            float2 o0, o1;
            o0.x = fast_sqrt(fabsf(x2v.x + p2r[2 * mt]     - 2.0f * c0.x) + 1e-14f);
            o0.y = fast_sqrt(fabsf(x2v.y + p2r[2 * mt]     - 2.0f * c0.y) + 1e-14f);
            o1.x = fast_sqrt(fabsf(x2v.x + p2r[2 * mt + 1] - 2.0f * c1.x) + 1e-14f);
            o1.y = fast_sqrt(fabsf(x2v.y + p2r[2 * mt + 1] - 2.0f * c1.y) + 1e-14f);
            *(float2*)&out[base + (long)m0 * SP_OUT]       = o0;
            *(float2*)&out[base + (long)(m0 + 8) * SP_OUT] = o1;
        }
    }
}

__global__ void __launch_bounds__(128, 2) l2conv_main_kernel(float* __restrict__ out) {
    extern __shared__ char smem[];
    if (blockIdx.x < NFULL)
        l2_tile<128>(out, smem, blockIdx.x * 128);
    else
        l2_tile<64>(out, smem, FULLPOS + (blockIdx.x - NFULL) * 64);
}

// ---------------- launch ----------------
extern "C" void kernel_launch(void* const* d_in, const int* in_sizes, int n_in,
                              void* d_out, int out_size) {
    const float* xs = (const float*)d_in[0];
    const float* fv = (const float*)d_in[1];
    if (n_in >= 2 && in_sizes[0] == 128 * 128 * 27) {  // robust to input ordering
        xs = (const float*)d_in[1];
        fv = (const float*)d_in[0];
    }
    cudaFuncSetAttribute(l2conv_main_kernel,
                         cudaFuncAttributeMaxDynamicSharedMemorySize, SMEM_BYTES);
    xprep_kernel<<<BATCH * 24 * 24, 256>>>(xs);
    wp2_kernel<<<NF, 128>>>(fv);
    l2conv_main_kernel<<<NGRID, 128, SMEM_BYTES>>>((float*)d_out);
}